// round 4
// baseline (speedup 1.0000x reference)
#include <cuda_runtime.h>
#include <cuda_bf16.h>

// ============================================================================
// BilinearChebConv: out[o] = sum_{i,j} theta[i,j,0,o] * (Tr_i @ X @ Tc_j) + bias
// with Tr/Tc = Chebyshev bases of Lr/Lc up to order 4. M = N = 1536.
//
// Decomposition (all 1536x1536x1536 fp32 GEMMs):
//   cheb rows/cols : T2 = 2*L@L - I ; T3 = 2*L@T2 - L ; T4 = 2*L@T3 - T2
//   stage B        : Y_i = Tr_i @ X          (i = 1..4; Y_0 = X)
//   stage C        : Z_ij = Y_i @ Tc_j       (j = 1..4; Z_i0 = Y_i)
//   combine        : out[o,m,n] = bias[o] + sum_ij theta[ijo] * Z_ij[m,n]
// ============================================================================

#define MM 1536
#define PLANE ((size_t)MM * MM)

// Scratch (device globals; no runtime allocation)
__device__ float g_Tr[3 * (size_t)MM * MM];   // T2, T3, T4 (rows)
__device__ float g_Tc[3 * (size_t)MM * MM];   // T2, T3, T4 (cols)
__device__ float g_Y [4 * (size_t)MM * MM];   // Y1..Y4
__device__ float g_Z [20 * (size_t)MM * MM];  // Z_ij, j=1..4, idx = i*4 + (j-1)

// ---------------------------------------------------------------------------
// Tiled fp32 GEMM core: C = alpha*A@B + beta*D + gamma*I   (all MM x MM)
// BM=BN=128, BK=16, 256 threads, 8x8 per-thread microtile.
// ---------------------------------------------------------------------------
#define BM 128
#define BN 128
#define BK 16
#define TM 8
#define TN 8

__device__ __forceinline__ void gemm_tile(
    const float* __restrict__ A, const float* __restrict__ B,
    float* __restrict__ C, const float* __restrict__ D,
    float alpha, float beta, float gamma)
{
    __shared__ float As[BK][BM + 4];   // A stored transposed: As[k][m]
    __shared__ float Bs[BK][BN];

    const int tid = threadIdx.x;            // 0..255
    const int bm  = blockIdx.y * BM;
    const int bn  = blockIdx.x * BN;

    const int tx = tid & 15;                // 0..15 -> n microtile
    const int ty = tid >> 4;                // 0..15 -> m microtile

    // A tile loads: 128x16 floats; tid/4 -> row (0..63, +64), (tid&3)*4 -> k col
    const int arow  = tid >> 2;
    const int acol4 = (tid & 3) * 4;
    // B tile loads: 16x128 floats; tid/32 -> k row (0..7, +8), (tid&31)*4 -> n col
    const int brow  = tid >> 5;
    const int bcol4 = (tid & 31) * 4;

    float acc[TM][TN];
    #pragma unroll
    for (int i = 0; i < TM; i++)
        #pragma unroll
        for (int j = 0; j < TN; j++) acc[i][j] = 0.0f;

    for (int k0 = 0; k0 < MM; k0 += BK) {
        #pragma unroll
        for (int r = 0; r < 2; r++) {
            const int row = arow + r * 64;
            float4 a4 = *(const float4*)&A[(size_t)(bm + row) * MM + k0 + acol4];
            As[acol4 + 0][row] = a4.x;
            As[acol4 + 1][row] = a4.y;
            As[acol4 + 2][row] = a4.z;
            As[acol4 + 3][row] = a4.w;
        }
        #pragma unroll
        for (int r = 0; r < 2; r++) {
            const int row = brow + r * 8;
            *(float4*)&Bs[row][bcol4] =
                *(const float4*)&B[(size_t)(k0 + row) * MM + bn + bcol4];
        }
        __syncthreads();

        #pragma unroll
        for (int kk = 0; kk < BK; kk++) {
            float ra[TM], rb[TN];
            #pragma unroll
            for (int i = 0; i < TM; i += 4)
                *(float4*)&ra[i] = *(const float4*)&As[kk][ty * TM + i];
            #pragma unroll
            for (int j = 0; j < TN; j += 4)
                *(float4*)&rb[j] = *(const float4*)&Bs[kk][tx * TN + j];
            #pragma unroll
            for (int i = 0; i < TM; i++)
                #pragma unroll
                for (int j = 0; j < TN; j++)
                    acc[i][j] = fmaf(ra[i], rb[j], acc[i][j]);
        }
        __syncthreads();
    }

    // Epilogue
    #pragma unroll
    for (int i = 0; i < TM; i++) {
        const int row = bm + ty * TM + i;
        #pragma unroll
        for (int j = 0; j < TN; j += 4) {
            const int col = bn + tx * TN + j;
            float4 v;
            v.x = alpha * acc[i][j + 0];
            v.y = alpha * acc[i][j + 1];
            v.z = alpha * acc[i][j + 2];
            v.w = alpha * acc[i][j + 3];
            if (D != nullptr) {
                float4 d4 = *(const float4*)&D[(size_t)row * MM + col];
                v.x += beta * d4.x;
                v.y += beta * d4.y;
                v.z += beta * d4.z;
                v.w += beta * d4.w;
            }
            if (gamma != 0.0f) {
                if (row == col + 0) v.x += gamma;
                if (row == col + 1) v.y += gamma;
                if (row == col + 2) v.z += gamma;
                if (row == col + 3) v.w += gamma;
            }
            *(float4*)&C[(size_t)row * MM + col] = v;
        }
    }
}

// ---------------------------------------------------------------------------
// Chebyshev step: z=0 rows (Lr), z=1 cols (Lc). step in {2,3,4}.
// ---------------------------------------------------------------------------
__global__ __launch_bounds__(256)
void cheb_step_kernel(int step, const float* __restrict__ Lr,
                      const float* __restrict__ Lc)
{
    const float* L = (blockIdx.z == 0) ? Lr : Lc;
    float* T = (blockIdx.z == 0) ? g_Tr : g_Tc;

    const float* Bm;
    float*       C;
    const float* D;
    float beta = -1.0f, gamma = 0.0f;

    if (step == 2) {            // T2 = 2*L@L - I
        Bm = L;                C = T;             D = nullptr; beta = 0.0f; gamma = -1.0f;
    } else if (step == 3) {     // T3 = 2*L@T2 - L
        Bm = T;                C = T + PLANE;     D = L;
    } else {                    // T4 = 2*L@T3 - T2
        Bm = T + PLANE;        C = T + 2 * PLANE; D = T;
    }
    gemm_tile(L, Bm, C, D, 2.0f, beta, gamma);
}

// ---------------------------------------------------------------------------
// Stage B: Y_i = Tr_i @ X   (grid.z = 4, i = z+1)
// ---------------------------------------------------------------------------
__global__ __launch_bounds__(256)
void stageB_kernel(const float* __restrict__ Lr, const float* __restrict__ X)
{
    const int z = blockIdx.z;          // 0..3  -> i = z+1
    const float* A = (z == 0) ? Lr : (g_Tr + (size_t)(z - 1) * PLANE);
    float* C = g_Y + (size_t)z * PLANE;
    gemm_tile(A, X, C, nullptr, 1.0f, 0.0f, 0.0f);
}

// ---------------------------------------------------------------------------
// Stage C: Z_ij = Y_i @ Tc_j   (grid.z = 20; i = z/4, j = z%4 + 1)
// ---------------------------------------------------------------------------
__global__ __launch_bounds__(256)
void stageC_kernel(const float* __restrict__ X, const float* __restrict__ Lc)
{
    const int z = blockIdx.z;          // 0..19
    const int i = z >> 2;              // 0..4
    const int jm1 = z & 3;             // 0..3 -> j = jm1+1
    const float* A = (i == 0) ? X : (g_Y + (size_t)(i - 1) * PLANE);
    const float* B = (jm1 == 0) ? Lc : (g_Tc + (size_t)(jm1 - 1) * PLANE);
    float* C = g_Z + (size_t)z * PLANE;
    gemm_tile(A, B, C, nullptr, 1.0f, 0.0f, 0.0f);
}

// ---------------------------------------------------------------------------
// Combine: out[o,m,n] = bias[o] + sum_{i,j} theta[(i*5+j)*32+o] * plane_ij[m,n]
// plane(i,0) = Y_i (X for i=0), plane(i,j>=1) = Z[i*4+j-1].
// Each thread handles 4 consecutive pixels (float4).
// ---------------------------------------------------------------------------
__global__ __launch_bounds__(256)
void combine_kernel(const float* __restrict__ X,
                    const float* __restrict__ theta,
                    const float* __restrict__ bias,
                    float* __restrict__ out)
{
    __shared__ float th[25][32];
    __shared__ float bs[32];

    const int tid = threadIdx.x;
    for (int t = tid; t < 25 * 32; t += blockDim.x) ((float*)th)[t] = theta[t];
    if (tid < 32) bs[tid] = bias[tid];
    __syncthreads();

    const size_t idx4 = ((size_t)blockIdx.x * blockDim.x + tid) * 4;
    if (idx4 >= PLANE) return;   // exact coverage: PLANE = 2304 * 256 * 4

    float4 v[25];
    #pragma unroll
    for (int i = 0; i < 5; i++) {
        const float* p0 = (i == 0) ? X : (g_Y + (size_t)(i - 1) * PLANE);
        v[i * 5 + 0] = *(const float4*)&p0[idx4];
        #pragma unroll
        for (int j = 1; j < 5; j++)
            v[i * 5 + j] = *(const float4*)&g_Z[(size_t)(i * 4 + j - 1) * PLANE + idx4];
    }

    #pragma unroll
    for (int o = 0; o < 32; o++) {
        float4 s;
        s.x = s.y = s.z = s.w = bs[o];
        #pragma unroll
        for (int t = 0; t < 25; t++) {
            const float w = th[t][o];
            s.x = fmaf(w, v[t].x, s.x);
            s.y = fmaf(w, v[t].y, s.y);
            s.z = fmaf(w, v[t].z, s.z);
            s.w = fmaf(w, v[t].w, s.w);
        }
        *(float4*)&out[(size_t)o * PLANE + idx4] = s;
    }
}

// ---------------------------------------------------------------------------
// Launch
// ---------------------------------------------------------------------------
extern "C" void kernel_launch(void* const* d_in, const int* in_sizes, int n_in,
                              void* d_out, int out_size)
{
    const float* X     = (const float*)d_in[0];   // (1, M, N)
    const float* Lr    = (const float*)d_in[1];   // (M, M)
    const float* Lc    = (const float*)d_in[2];   // (N, N)
    const float* theta = (const float*)d_in[3];   // (5, 5, 1, 32)
    const float* bias  = (const float*)d_in[4];   // (32,)
    float* out = (float*)d_out;                   // (32, M, N)

    const dim3 blk(256);
    const dim3 g2 (MM / BN, MM / BM, 2);
    const dim3 g4 (MM / BN, MM / BM, 4);
    const dim3 g20(MM / BN, MM / BM, 20);

    // Chebyshev bases (rows+cols batched in z; steps are sequentially dependent)
    cheb_step_kernel<<<g2, blk>>>(2, Lr, Lc);
    cheb_step_kernel<<<g2, blk>>>(3, Lr, Lc);
    cheb_step_kernel<<<g2, blk>>>(4, Lr, Lc);

    // Stage B: Y_i = Tr_i @ X
    stageB_kernel<<<g4, blk>>>(Lr, X);

    // Stage C: Z_ij = Y_i @ Tc_j
    stageC_kernel<<<g20, blk>>>(X, Lc);

    // Combine into 32 output channels
    const int nblocks = (int)(PLANE / (256 * 4));
    combine_kernel<<<nblocks, 256>>>(X, theta, bias, out);
}

// round 6
// speedup vs baseline: 1.9254x; 1.9254x over previous
#include <cuda_runtime.h>
#include <cuda_bf16.h>
#include <cstdint>

// ============================================================================
// BilinearChebConv via mma.sync bf16-split GEMMs (compute_103-safe PTX only).
//
// out[o] = sum_{i,j} theta[i,j,o] * (Tr_i @ X @ Tc_j) + bias,
// Tr/Tc = Chebyshev bases of symmetric Lr/Lc (order 4), M = N = 1536.
//
// Every 1536^3 GEMM runs on tensor cores (mma.sync m16n8k16 bf16->fp32) with a
// 2-term bf16 split: A@B ~= Ah@Bh + Ah@Bl + Al@Bh  (error ~2^-17 per product).
// All Chebyshev matrices are symmetric => B^T = B, so both operands are fed
// K-major. Only X needs a one-time transpose (B operand of stage B).
// NOTE: tcgen05 is NOT available (harness PTX targets compute_103 without 'a').
// ============================================================================

#define MM 1536
#define PLANE ((size_t)MM * MM)

#define BM 128
#define BN 128
#define BK 32
#define NCH (MM / BK)               // 48 k-chunks
#define ROWB 80                     // 32 bf16 = 64B data, padded to 80B stride
#define TILEB (128 * ROWB)          // 10240 B per tile
#define STAGEB (4 * TILEB)          // Ah, Al, Bh, Bl
#define SMEM_TOTAL (2 * STAGEB)     // double buffered: 81920 B

// ---------------------------------------------------------------------------
// Scratch (device globals; no runtime allocation)
// ---------------------------------------------------------------------------
// Row/col Chebyshev splits: plane 0 = L, planes 1..3 = T2..T4
__device__ __nv_bfloat16 g_Trh[4 * (size_t)MM * MM];
__device__ __nv_bfloat16 g_Trl[4 * (size_t)MM * MM];
__device__ __nv_bfloat16 g_Tch[4 * (size_t)MM * MM];
__device__ __nv_bfloat16 g_Tcl[4 * (size_t)MM * MM];
// X splits (normal for stage-C A operand; transposed for stage-B B operand)
__device__ __nv_bfloat16 g_Xh [(size_t)MM * MM];
__device__ __nv_bfloat16 g_Xl [(size_t)MM * MM];
__device__ __nv_bfloat16 g_Xth[(size_t)MM * MM];
__device__ __nv_bfloat16 g_Xtl[(size_t)MM * MM];
// Stage B outputs
__device__ float         g_Yf[4 * (size_t)MM * MM];
__device__ __nv_bfloat16 g_Yh[4 * (size_t)MM * MM];
__device__ __nv_bfloat16 g_Yl[4 * (size_t)MM * MM];
// fp32 T2 (beta source for T4 step), row + col
__device__ float g_T2f[2 * (size_t)MM * MM];
// Stage C outputs
__device__ float g_Z[20 * (size_t)MM * MM];

// ---------------------------------------------------------------------------
// PTX helpers (all valid on plain compute_103)
// ---------------------------------------------------------------------------
__device__ __forceinline__ uint32_t smem_u32(const void* p) {
    uint32_t a;
    asm("{ .reg .u64 t; cvta.to.shared.u64 t, %1; cvt.u32.u64 %0, t; }"
        : "=r"(a) : "l"(p));
    return a;
}

__device__ __forceinline__ void cp16(uint32_t dst, const void* src) {
    asm volatile("cp.async.cg.shared.global [%0], [%1], 16;"
                 :: "r"(dst), "l"(src) : "memory");
}
#define CP_COMMIT() asm volatile("cp.async.commit_group;" ::: "memory")
#define CP_WAIT(n)  asm volatile("cp.async.wait_group %0;" :: "n"(n) : "memory")

#define LDSM4(r0, r1, r2, r3, addr) \
    asm volatile("ldmatrix.sync.aligned.m8n8.x4.shared.b16 {%0,%1,%2,%3}, [%4];" \
                 : "=r"(r0), "=r"(r1), "=r"(r2), "=r"(r3) : "r"(addr))

#define MMA16816(d, a, b0, b1) \
    asm volatile("mma.sync.aligned.m16n8k16.row.col.f32.bf16.bf16.f32 " \
                 "{%0,%1,%2,%3}, {%4,%5,%6,%7}, {%8,%9}, {%0,%1,%2,%3};" \
                 : "+f"((d)[0]), "+f"((d)[1]), "+f"((d)[2]), "+f"((d)[3]) \
                 : "r"((a)[0]), "r"((a)[1]), "r"((a)[2]), "r"((a)[3]), \
                   "r"(b0), "r"(b1))

// ---------------------------------------------------------------------------
// Stage loader: Ah/Al (bm rows) + Bh/Bl (bn rows), 32 bf16 of K per row,
// into 80B-strided SMEM rows. 512 x 16B chunks per matrix, 256 threads.
// ---------------------------------------------------------------------------
__device__ __forceinline__ void load_stage(
    uint32_t base, int kc,
    const __nv_bfloat16* __restrict__ Ah, const __nv_bfloat16* __restrict__ Al,
    const __nv_bfloat16* __restrict__ Bh, const __nv_bfloat16* __restrict__ Bl,
    int bm, int bn, int tid)
{
    const __nv_bfloat16* mats[4] = { Ah, Al, Bh, Bl };
    const int r0s[4] = { bm, bm, bn, bn };
    #pragma unroll
    for (int m = 0; m < 4; ++m) {
        const __nv_bfloat16* g = mats[m];
        const int r0 = r0s[m];
        #pragma unroll
        for (int it = 0; it < 2; ++it) {
            const int u = it * 256 + tid;        // 0..511
            const int row = u >> 2, cc = u & 3;
            cp16(base + m * TILEB + row * ROWB + cc * 16,
                 g + (size_t)(r0 + row) * MM + kc * BK + cc * 8);
        }
    }
    CP_COMMIT();
}

// ---------------------------------------------------------------------------
// GEMM core: C(128x128 per CTA) = alpha*(A@B) + beta*Df + gamma*I
// A: [M,K] bf16 hi/lo ; B stored as B^T: [N,K] bf16 hi/lo (symmetric mats).
// Writes fp32 (Cf) and/or bf16 split (Chi/Clo).
// ---------------------------------------------------------------------------
__device__ void gemm_core(
    const __nv_bfloat16* __restrict__ Ah, const __nv_bfloat16* __restrict__ Al,
    const __nv_bfloat16* __restrict__ Bh, const __nv_bfloat16* __restrict__ Bl,
    float* __restrict__ Cf, __nv_bfloat16* __restrict__ Chi,
    __nv_bfloat16* __restrict__ Clo, const float* __restrict__ Df,
    float alpha, float beta, float gamma)
{
    extern __shared__ char smem[];
    const int tid  = threadIdx.x;
    const int wid  = tid >> 5, lane = tid & 31;
    const int wr   = wid & 3;          // warp row: 4 x 32 rows
    const int wc   = wid >> 2;         // warp col: 2 x 64 cols
    const int bm   = blockIdx.y * BM;
    const int bn   = blockIdx.x * BN;
    const uint32_t sb = smem_u32(smem);

    float acc[2][8][4];
    #pragma unroll
    for (int mt = 0; mt < 2; ++mt)
        #pragma unroll
        for (int nt = 0; nt < 8; ++nt)
            #pragma unroll
            for (int q = 0; q < 4; ++q) acc[mt][nt][q] = 0.0f;

    // ldmatrix per-thread address components (row within 16-row block, k half)
    const int lrow = lane & 15;
    const int kh16 = (lane >> 4) * 16;           // byte offset for k-half

    load_stage(sb, 0, Ah, Al, Bh, Bl, bm, bn, tid);

    for (int c = 0; c < NCH; ++c) {
        const int s = c & 1;
        if (c + 1 < NCH) {
            load_stage(sb + ((c + 1) & 1) * STAGEB, c + 1, Ah, Al, Bh, Bl, bm, bn, tid);
            CP_WAIT(1);
        } else {
            CP_WAIT(0);
        }
        __syncthreads();

        const uint32_t stage = sb + s * STAGEB;
        #pragma unroll
        for (int k16 = 0; k16 < 2; ++k16) {
            const uint32_t kb = k16 * 32 + kh16;
            uint32_t ah[2][4], al[2][4], bh[4][4], bl[4][4];
            #pragma unroll
            for (int mt = 0; mt < 2; ++mt) {
                const uint32_t ro = (wr * 32 + mt * 16 + lrow) * ROWB + kb;
                LDSM4(ah[mt][0], ah[mt][1], ah[mt][2], ah[mt][3], stage + ro);
                LDSM4(al[mt][0], al[mt][1], al[mt][2], al[mt][3], stage + TILEB + ro);
            }
            #pragma unroll
            for (int nt2 = 0; nt2 < 4; ++nt2) {
                const uint32_t ro = (wc * 64 + nt2 * 16 + lrow) * ROWB + kb;
                LDSM4(bh[nt2][0], bh[nt2][1], bh[nt2][2], bh[nt2][3],
                      stage + 2 * TILEB + ro);
                LDSM4(bl[nt2][0], bl[nt2][1], bl[nt2][2], bl[nt2][3],
                      stage + 3 * TILEB + ro);
            }
            #pragma unroll
            for (int mt = 0; mt < 2; ++mt)
                #pragma unroll
                for (int nt = 0; nt < 8; ++nt) {
                    const int n2 = nt >> 1, w = nt & 1;
                    MMA16816(acc[mt][nt], ah[mt], bh[n2][w], bh[n2][w + 2]);
                    MMA16816(acc[mt][nt], ah[mt], bl[n2][w], bl[n2][w + 2]);
                    MMA16816(acc[mt][nt], al[mt], bh[n2][w], bh[n2][w + 2]);
                }
        }
        __syncthreads();
    }

    // Epilogue: frag (mt,nt) half h -> row bm+wr*32+mt*16+(lane>>2)+h*8,
    //                                  col bn+wc*64+nt*8+(lane&3)*2
    #pragma unroll
    for (int mt = 0; mt < 2; ++mt)
        #pragma unroll
        for (int h = 0; h < 2; ++h) {
            const int r = bm + wr * 32 + mt * 16 + (lane >> 2) + h * 8;
            #pragma unroll
            for (int nt = 0; nt < 8; ++nt) {
                const int col = bn + wc * 64 + nt * 8 + (lane & 3) * 2;
                const size_t go = (size_t)r * MM + col;
                float v0 = alpha * acc[mt][nt][h * 2 + 0];
                float v1 = alpha * acc[mt][nt][h * 2 + 1];
                if (Df != nullptr) {
                    float2 d = *(const float2*)(Df + go);
                    v0 += beta * d.x;
                    v1 += beta * d.y;
                }
                if (gamma != 0.0f) {
                    if (r == col)     v0 += gamma;
                    if (r == col + 1) v1 += gamma;
                }
                if (Cf != nullptr)
                    *(float2*)(Cf + go) = make_float2(v0, v1);
                if (Chi != nullptr) {
                    __nv_bfloat16 h0 = __float2bfloat16(v0);
                    __nv_bfloat16 h1 = __float2bfloat16(v1);
                    __nv_bfloat16 l0 = __float2bfloat16(v0 - __bfloat162float(h0));
                    __nv_bfloat16 l1 = __float2bfloat16(v1 - __bfloat162float(h1));
                    __nv_bfloat162 hp; hp.x = h0; hp.y = h1;
                    __nv_bfloat162 lp; lp.x = l0; lp.y = l1;
                    *(__nv_bfloat162*)(Chi + go) = hp;
                    *(__nv_bfloat162*)(Clo + go) = lp;
                }
            }
        }
}

// ---------------------------------------------------------------------------
// Unified GEMM dispatcher.
// which: 0=T2, 1=T3, 2=T4 (z: 0 rows / 1 cols), 3=stageB (z=i-1), 4=stageC
// ---------------------------------------------------------------------------
__global__ __launch_bounds__(256)
void tc_gemm_kernel(int which, const float* __restrict__ LrF,
                    const float* __restrict__ LcF)
{
    const int z = blockIdx.z;
    const __nv_bfloat16 *Ah, *Al, *Bh, *Bl;
    float* Cf = nullptr;
    __nv_bfloat16 *Chi = nullptr, *Clo = nullptr;
    const float* Df = nullptr;
    float alpha = 1.f, beta = 0.f, gamma = 0.f;

    if (which <= 2) {
        __nv_bfloat16* Th = z ? g_Tch : g_Trh;
        __nv_bfloat16* Tl = z ? g_Tcl : g_Trl;
        const float* Lf = z ? LcF : LrF;
        Ah = Th; Al = Tl;            // A = L (hi/lo)
        alpha = 2.f;
        if (which == 0) {            // T2 = 2*L@L - I
            Bh = Th; Bl = Tl;
            gamma = -1.f;
            Cf = g_T2f + (size_t)z * PLANE;
            Chi = Th + PLANE; Clo = Tl + PLANE;
        } else if (which == 1) {     // T3 = 2*L@T2 - L
            Bh = Th + PLANE; Bl = Tl + PLANE;
            Df = Lf; beta = -1.f;
            Chi = Th + 2 * PLANE; Clo = Tl + 2 * PLANE;
        } else {                     // T4 = 2*L@T3 - T2
            Bh = Th + 2 * PLANE; Bl = Tl + 2 * PLANE;
            Df = g_T2f + (size_t)z * PLANE; beta = -1.f;
            Chi = Th + 3 * PLANE; Clo = Tl + 3 * PLANE;
        }
    } else if (which == 3) {         // Y_{z+1} = Tr_{z+1} @ X   (B = X => B^T = Xt)
        Ah = g_Trh + (size_t)z * PLANE; Al = g_Trl + (size_t)z * PLANE;
        Bh = g_Xth; Bl = g_Xtl;
        Cf  = g_Yf + (size_t)z * PLANE;
        Chi = g_Yh + (size_t)z * PLANE;
        Clo = g_Yl + (size_t)z * PLANE;
    } else {                         // Z_ij = Y_i @ Tc_j (Tc symmetric => B^T = Tc)
        const int i = z >> 2, jm = z & 3;
        Ah = i ? (g_Yh + (size_t)(i - 1) * PLANE) : g_Xh;
        Al = i ? (g_Yl + (size_t)(i - 1) * PLANE) : g_Xl;
        Bh = g_Tch + (size_t)jm * PLANE;
        Bl = g_Tcl + (size_t)jm * PLANE;
        Cf = g_Z + (size_t)z * PLANE;
    }
    gemm_core(Ah, Al, Bh, Bl, Cf, Chi, Clo, Df, alpha, beta, gamma);
}

// ---------------------------------------------------------------------------
// Split Lr/Lc into bf16 hi/lo (plane 0 of the Tr/Tc arrays).
// ---------------------------------------------------------------------------
__global__ __launch_bounds__(256)
void split_lrlc_kernel(const float* __restrict__ Lr, const float* __restrict__ Lc)
{
    const float* src = blockIdx.y ? Lc : Lr;
    __nv_bfloat16* h = blockIdx.y ? g_Tch : g_Trh;
    __nv_bfloat16* l = blockIdx.y ? g_Tcl : g_Trl;
    const size_t i4 = ((size_t)blockIdx.x * 256 + threadIdx.x) * 4;
    float4 v = *(const float4*)(src + i4);
    union { __nv_bfloat16 b[4]; float2 f; } hb, lb;
    float vv[4] = { v.x, v.y, v.z, v.w };
    #pragma unroll
    for (int j = 0; j < 4; ++j) {
        __nv_bfloat16 hh = __float2bfloat16(vv[j]);
        hb.b[j] = hh;
        lb.b[j] = __float2bfloat16(vv[j] - __bfloat162float(hh));
    }
    *(float2*)(h + i4) = hb.f;
    *(float2*)(l + i4) = lb.f;
}

// ---------------------------------------------------------------------------
// Split X (normal) + split X^T (transposed) in one pass. 32x32 tiles.
// ---------------------------------------------------------------------------
__global__ __launch_bounds__(256)
void splitX_kernel(const float* __restrict__ X)
{
    __shared__ float tile[32][33];
    const int tx = threadIdx.x, ty = threadIdx.y;   // (32, 8)
    const int bx = blockIdx.x * 32, by = blockIdx.y * 32;

    #pragma unroll
    for (int r = 0; r < 4; ++r) {
        const int y = by + ty + r * 8;
        const float v = X[(size_t)y * MM + bx + tx];
        tile[ty + r * 8][tx] = v;
        __nv_bfloat16 hh = __float2bfloat16(v);
        g_Xh[(size_t)y * MM + bx + tx] = hh;
        g_Xl[(size_t)y * MM + bx + tx] = __float2bfloat16(v - __bfloat162float(hh));
    }
    __syncthreads();
    #pragma unroll
    for (int r = 0; r < 4; ++r) {
        const float v = tile[tx][ty + r * 8];       // X[by+tx][bx+ty+r*8]
        const size_t o = (size_t)(bx + ty + r * 8) * MM + by + tx;
        __nv_bfloat16 hh = __float2bfloat16(v);
        g_Xth[o] = hh;
        g_Xtl[o] = __float2bfloat16(v - __bfloat162float(hh));
    }
}

// ---------------------------------------------------------------------------
// Combine: out[o,m,n] = bias[o] + sum_{i,j} theta[(i*5+j)*32+o] * plane_ij[m,n]
// ---------------------------------------------------------------------------
__global__ __launch_bounds__(256)
void combine_kernel(const float* __restrict__ X,
                    const float* __restrict__ theta,
                    const float* __restrict__ bias,
                    float* __restrict__ out)
{
    __shared__ float th[25][32];
    __shared__ float bs[32];

    const int tid = threadIdx.x;
    for (int t = tid; t < 25 * 32; t += blockDim.x) ((float*)th)[t] = theta[t];
    if (tid < 32) bs[tid] = bias[tid];
    __syncthreads();

    const size_t idx4 = ((size_t)blockIdx.x * blockDim.x + tid) * 4;
    if (idx4 >= PLANE) return;

    float4 v[25];
    #pragma unroll
    for (int i = 0; i < 5; i++) {
        const float* p0 = (i == 0) ? X : (g_Yf + (size_t)(i - 1) * PLANE);
        v[i * 5 + 0] = *(const float4*)&p0[idx4];
        #pragma unroll
        for (int j = 1; j < 5; j++)
            v[i * 5 + j] = *(const float4*)&g_Z[(size_t)(i * 4 + j - 1) * PLANE + idx4];
    }

    #pragma unroll
    for (int o = 0; o < 32; o++) {
        float4 s;
        s.x = s.y = s.z = s.w = bs[o];
        #pragma unroll
        for (int t = 0; t < 25; t++) {
            const float w = th[t][o];
            s.x = fmaf(w, v[t].x, s.x);
            s.y = fmaf(w, v[t].y, s.y);
            s.z = fmaf(w, v[t].z, s.z);
            s.w = fmaf(w, v[t].w, s.w);
        }
        *(float4*)&out[(size_t)o * PLANE + idx4] = s;
    }
}

// ---------------------------------------------------------------------------
// Launch
// ---------------------------------------------------------------------------
extern "C" void kernel_launch(void* const* d_in, const int* in_sizes, int n_in,
                              void* d_out, int out_size)
{
    const float* X     = (const float*)d_in[0];   // (1, M, N)
    const float* Lr    = (const float*)d_in[1];   // (M, M), symmetric
    const float* Lc    = (const float*)d_in[2];   // (N, N), symmetric
    const float* theta = (const float*)d_in[3];   // (5, 5, 1, 32)
    const float* bias  = (const float*)d_in[4];   // (32,)
    float* out = (float*)d_out;                   // (32, M, N)

    cudaFuncSetAttribute(tc_gemm_kernel,
                         cudaFuncAttributeMaxDynamicSharedMemorySize, SMEM_TOTAL);

    const dim3 blk(256);
    const int pb = (int)(PLANE / (256 * 4));      // 2304

    // Input splits
    split_lrlc_kernel<<<dim3(pb, 2), blk>>>(Lr, Lc);
    splitX_kernel<<<dim3(MM / 32, MM / 32), dim3(32, 8)>>>(X);

    // Chebyshev recursion (rows + cols batched via z; steps dependent)
    const dim3 g2(MM / BN, MM / BM, 2);
    tc_gemm_kernel<<<g2, blk, SMEM_TOTAL>>>(0, Lr, Lc);
    tc_gemm_kernel<<<g2, blk, SMEM_TOTAL>>>(1, Lr, Lc);
    tc_gemm_kernel<<<g2, blk, SMEM_TOTAL>>>(2, Lr, Lc);

    // Stage B: Y_i = Tr_i @ X
    tc_gemm_kernel<<<dim3(MM / BN, MM / BM, 4), blk, SMEM_TOTAL>>>(3, Lr, Lc);

    // Stage C: Z_ij = Y_i @ Tc_j
    tc_gemm_kernel<<<dim3(MM / BN, MM / BM, 20), blk, SMEM_TOTAL>>>(4, Lr, Lc);

    // Combine into 32 output channels
    combine_kernel<<<pb, blk>>>(X, theta, bias, out);
}